// round 3
// baseline (speedup 1.0000x reference)
#include <cuda_runtime.h>
#include <cstdint>

// Problem constants (from reference): B=32, S=1024, D=512
#define BB 32
#define SS 1024
#define DD 512
#define DV4 (DD / 4)   // 128 float4 per row

// Scratch (allocation-free per harness rules)
__device__ int g_ends[BB * SS];   // inclusive cumsum of clamped durations, per batch
__device__ int g_totals[BB];      // total_lengths per batch

// ---------------------------------------------------------------------------
// Kernel A: per-batch duration round/clamp + inclusive scan.
// One block per batch, 1024 threads (one per s).
// ---------------------------------------------------------------------------
__global__ void __launch_bounds__(1024)
durscan_kernel(const float* __restrict__ durations, const int* __restrict__ scale_raw)
{
    const int b   = blockIdx.x;
    const int tid = threadIdx.x;

    // duration_scale dtype is ambiguous (python int 1 vs float 1.0).
    // Heuristic: interpret the raw 32-bit word as float; if it's in a sane
    // magnitude range use it, otherwise treat the word as an int value.
    const int   iv = scale_raw[0];
    const float fv = __int_as_float(iv);
    const float af = fabsf(fv);
    const float scale = (af >= 1e-6f && af <= 1e6f) ? fv : (float)iv;

    const float dv = durations[b * SS + tid];
    int d = (int)(dv * scale + 0.5f);   // truncation toward zero == astype(int32) for nonneg
    if (d < 1) d = 1;

    // Inclusive scan: warp shuffles + cross-warp smem.
    int v = d;
    const int lane = tid & 31;
    const int warp = tid >> 5;
    #pragma unroll
    for (int o = 1; o < 32; o <<= 1) {
        int n = __shfl_up_sync(0xffffffffu, v, o);
        if (lane >= o) v += n;
    }
    __shared__ int wsum[32];
    if (lane == 31) wsum[warp] = v;
    __syncthreads();
    if (warp == 0) {
        int w = wsum[lane];
        #pragma unroll
        for (int o = 1; o < 32; o <<= 1) {
            int n = __shfl_up_sync(0xffffffffu, w, o);
            if (lane >= o) w += n;
        }
        wsum[lane] = w;
    }
    __syncthreads();
    const int base = (warp > 0) ? wsum[warp - 1] : 0;
    const int e = base + v;

    g_ends[b * SS + tid] = e;
    if (tid == SS - 1) g_totals[b] = e;
}

// ---------------------------------------------------------------------------
// Kernel B: scatter-expand. One 128-thread block per (s, b) source row.
// Each thread holds one float4 of x[b][s] in a register and writes it to
// output rows [start, end). Source read exactly once from DRAM; writes are
// fully coalesced 512B rows.
// ---------------------------------------------------------------------------
__global__ void __launch_bounds__(128)
scatter_kernel(const float4* __restrict__ x4, float4* __restrict__ out4, int T)
{
    const int s = blockIdx.x;
    const int b = blockIdx.y;

    const int end   = g_ends[b * SS + s];
    const int start = (s > 0) ? g_ends[b * SS + s - 1] : 0;

    const float4 v = x4[((size_t)b * SS + s) * DV4 + threadIdx.x];

    float4* dst = out4 + ((size_t)b * T + start) * DV4 + threadIdx.x;
    for (int r = start; r < end; ++r) {
        *dst = v;
        dst += DV4;
    }
}

// ---------------------------------------------------------------------------
// Kernel C: zero the masked tail rows (d_out is poisoned 0xAA) and emit
// total_lengths (as float) if the harness's out buffer includes them.
// One 128-thread block per output row; rows t < total[b] exit immediately.
// ---------------------------------------------------------------------------
__global__ void __launch_bounds__(128)
tail_kernel(float4* __restrict__ out4, int T, float* __restrict__ len_out, int write_len)
{
    const int row = blockIdx.x;          // 0 .. B*T-1
    const int b = row / T;
    const int t = row - b * T;
    const int tot = g_totals[b];

    if (write_len && t == 0 && threadIdx.x == 0)
        len_out[b] = (float)tot;

    if (t >= tot) {
        const float4 z = make_float4(0.f, 0.f, 0.f, 0.f);
        out4[(size_t)row * DV4 + threadIdx.x] = z;
    }
}

// ---------------------------------------------------------------------------
extern "C" void kernel_launch(void* const* d_in, const int* in_sizes, int n_in,
                              void* d_out, int out_size)
{
    const float4* x4    = (const float4*)d_in[0];   // x: (B,S,D) float32
    const float*  dur   = (const float*)d_in[1];    // durations: (B,S) float32
    const int*    scale = (const int*)d_in[2];      // duration_scale: scalar (dtype ambiguous)
    float* out = (float*)d_out;

    // Recover T (max total length) from out_size. Two possible layouts:
    //   out only:           out_size = B*T*D
    //   out + lengths tail: out_size = B*T*D + B   (mutually exclusive mod B*D)
    int T, has_len;
    if (out_size % (BB * DD) == 0) {
        T = out_size / (BB * DD);
        has_len = 0;
    } else {
        T = (out_size - BB) / (BB * DD);
        has_len = 1;
    }

    durscan_kernel<<<BB, 1024>>>(dur, scale);
    scatter_kernel<<<dim3(SS, BB), 128>>>(x4, (float4*)out, T);
    tail_kernel<<<BB * T, 128>>>((float4*)out, T, out + (size_t)BB * T * DD, has_len);
}

// round 5
// speedup vs baseline: 2.1721x; 2.1721x over previous
#include <cuda_runtime.h>
#include <cstdint>

// Problem constants (from reference): B=32, S=1024, D=512
#define BB 32
#define SS 1024
#define DD 512
#define DV4 (DD / 4)      // 128 float4 per row
#define TAILW 64          // s-blocks per batch sharing the tail zero-fill

// Scratch (allocation-free per harness rules)
__device__ int g_ends[BB * SS];   // inclusive cumsum of clamped durations, per batch
__device__ int g_totals[BB];      // total_lengths per batch

// ---------------------------------------------------------------------------
// Kernel A: per-batch duration round/clamp + inclusive scan.
// One block per batch, 1024 threads (one per s).
// Also emits total_lengths (as float) into the output buffer tail if present.
// ---------------------------------------------------------------------------
__global__ void __launch_bounds__(1024)
durscan_kernel(const float* __restrict__ durations, const int* __restrict__ scale_raw,
               float* __restrict__ len_out, int write_len)
{
    const int b   = blockIdx.x;
    const int tid = threadIdx.x;

    // duration_scale dtype is ambiguous (python int 1 vs float 1.0).
    // Interpret the raw 32-bit word as float; if it's in a sane magnitude
    // range use it, otherwise treat the word as an int value.
    const int   iv = scale_raw[0];
    const float fv = __int_as_float(iv);
    const float af = fabsf(fv);
    const float scale = (af >= 1e-6f && af <= 1e6f) ? fv : (float)iv;

    const float dv = durations[b * SS + tid];
    int d = (int)(dv * scale + 0.5f);   // trunc toward zero == astype(int32) for nonneg
    if (d < 1) d = 1;

    // Inclusive scan: warp shuffles + cross-warp smem.
    int v = d;
    const int lane = tid & 31;
    const int warp = tid >> 5;
    #pragma unroll
    for (int o = 1; o < 32; o <<= 1) {
        int n = __shfl_up_sync(0xffffffffu, v, o);
        if (lane >= o) v += n;
    }
    __shared__ int wsum[32];
    if (lane == 31) wsum[warp] = v;
    __syncthreads();
    if (warp == 0) {
        int w = wsum[lane];
        #pragma unroll
        for (int o = 1; o < 32; o <<= 1) {
            int n = __shfl_up_sync(0xffffffffu, w, o);
            if (lane >= o) w += n;
        }
        wsum[lane] = w;
    }
    __syncthreads();
    const int base = (warp > 0) ? wsum[warp - 1] : 0;
    const int e = base + v;

    g_ends[b * SS + tid] = e;
    if (tid == SS - 1) {
        g_totals[b] = e;
        if (write_len) len_out[b] = (float)e;
    }
}

// ---------------------------------------------------------------------------
// Kernel B: scatter-expand + fused tail zero-fill.
// One 128-thread block per (s, b) source row. Each thread holds one float4 of
// x[b][s] in a register and streams it to output rows [start, end).
// The last TAILW s-blocks of each batch additionally zero-fill the masked
// tail rows [tot, T) in a strided, balanced fashion (output is 0xAA-poisoned).
// ---------------------------------------------------------------------------
__global__ void __launch_bounds__(128)
scatter_kernel(const float4* __restrict__ x4, float4* __restrict__ out4, int T)
{
    const int s = blockIdx.x;
    const int b = blockIdx.y;

    const int end   = g_ends[b * SS + s];
    const int start = (s > 0) ? g_ends[b * SS + s - 1] : 0;

    const float4 v = __ldcs(&x4[((size_t)b * SS + s) * DV4 + threadIdx.x]);

    float4* dst = out4 + ((size_t)b * T + start) * DV4 + threadIdx.x;
    for (int r = start; r < end; ++r) {
        __stcs(dst, v);
        dst += DV4;
    }

    // Fused tail zero-fill: rows [tot, T) shared across the last TAILW blocks.
    if (s >= SS - TAILW) {
        const int tot = g_totals[b];
        const float4 z = make_float4(0.f, 0.f, 0.f, 0.f);
        for (int r = tot + (s - (SS - TAILW)); r < T; r += TAILW) {
            __stcs(out4 + ((size_t)b * T + r) * DV4 + threadIdx.x, z);
        }
    }
}

// ---------------------------------------------------------------------------
extern "C" void kernel_launch(void* const* d_in, const int* in_sizes, int n_in,
                              void* d_out, int out_size)
{
    const float4* x4    = (const float4*)d_in[0];   // x: (B,S,D) float32
    const float*  dur   = (const float*)d_in[1];    // durations: (B,S) float32
    const int*    scale = (const int*)d_in[2];      // duration_scale: scalar
    float* out = (float*)d_out;

    // Recover T (max total length) from out_size:
    //   out only:           out_size = B*T*D
    //   out + lengths tail: out_size = B*T*D + B
    int T, has_len;
    if (out_size % (BB * DD) == 0) {
        T = out_size / (BB * DD);
        has_len = 0;
    } else {
        T = (out_size - BB) / (BB * DD);
        has_len = 1;
    }

    durscan_kernel<<<BB, 1024>>>(dur, scale, out + (size_t)BB * T * DD, has_len);
    scatter_kernel<<<dim3(SS, BB), 128>>>(x4, (float4*)out, T);
}